// round 14
// baseline (speedup 1.0000x reference)
#include <cuda_runtime.h>

// ---------------------------------------------------------------------------
// Bit-exact fused SNN kernel, v12 = R12 (best, 2018us) + plain x layout.
// x stored [ic][32 rows][36 pad] -> x-load is float4 LDG/STS (was scalar),
// stage1 window loads are LDS.128 (was LDS.64), halving stage1 x-load
// instruction count. Conv chains byte-identical in value sequence.
// NO prefetch (R8/R9/R10/R11/R13 all regressed via register-cap spills).
// PROTECTED arithmetic (rel_err == 0.0 invariant):
//   conv: per-output sequential FMA in (ky, kx, ic) order
//   FC:   sequential FMA q = 0..799
//   LIF:  m' = fsub(fma(0.95, m, cur), reset)
//   pool-then-bias
// FFMA2 = two INDEPENDENT IEEE fma.rn; pairing never mixes chains.
// ---------------------------------------------------------------------------

#define T_STEPS 100
#define BATCH   256

typedef unsigned long long u64;

// smem layout (float offsets)
constexpr int OFF_W1  = 0;       // w1 cl [oc][ky][kx][ic2]          = 600
constexpr int OFF_B1  = 600;     // 12 (+4 pad)
constexpr int OFF_W1P = 616;     // paired w1 [oc][ry-1][kx][4]      = 960
constexpr int OFF_W2  = 1576;    // w2 cl [32][25][12]               = 9600
constexpr int OFF_B2  = 11176;   // 32
constexpr int OFF_W3  = 11208;   // [10][804]                        = 8040
constexpr int OFF_B3  = 19248;   // 12
constexpr int OFF_X   = 19260;   // x [2 ic][32 rows][36 pad]        = 2304
constexpr int OFF_S1A = 21564;   // spk1 A [col14][rp7][ic12][2]     = 2352
constexpr int OFF_S1B = 23916;   // spk1 B [col14][rp6][ic12][2]     = 2016
constexpr int OFF_S2  = 25932;   // 800 (oc*25 + i*5 + j)
constexpr int SMEM_FLOATS = 26732;
constexpr int SMEM_BYTES  = SMEM_FLOATS * 4;

constexpr int XR = 36;           // x row stride (floats)
constexpr int XIC = 32 * XR;     // x ic stride = 1152

__device__ __forceinline__ u64 pack2(float lo, float hi) {
    u64 r;
    asm("mov.b64 %0, {%1, %2};" : "=l"(r) : "f"(lo), "f"(hi));
    return r;
}
__device__ __forceinline__ void unpack2(float& lo, float& hi, u64 v) {
    asm("mov.b64 {%0, %1}, %2;" : "=f"(lo), "=f"(hi) : "l"(v));
}
// d.lo = fma.rn(a.lo, b.lo, d.lo); d.hi = fma.rn(a.hi, b.hi, d.hi)
__device__ __forceinline__ void ffma2(u64& d, u64 a, u64 b) {
    asm("fma.rn.f32x2 %0, %1, %2, %0;" : "+l"(d) : "l"(a), "l"(b));
}

__device__ __forceinline__ float lif_step(float& mem, float cur) {
    float reset = (mem > 1.0f) ? 1.0f : 0.0f;
    float mn = __fsub_rn(__fmaf_rn(0.95f, mem, cur), reset);
    mem = mn;
    return (mn > 1.0f) ? 1.0f : 0.0f;
}

__device__ __forceinline__ void fc_stage(const float* __restrict__ s,
                                         float& mem3, int t, int b, int k,
                                         float* __restrict__ out) {
    const float4* wr = reinterpret_cast<const float4*>(s + OFF_W3 + k * 804);
    const float4* xv = reinterpret_cast<const float4*>(s + OFF_S2);
    float acc = 0.f;
    #pragma unroll 4
    for (int q = 0; q < 200; q++) {
        float4 w = wr[q], x = xv[q];
        acc = fmaf(x.x, w.x, acc);
        acc = fmaf(x.y, w.y, acc);
        acc = fmaf(x.z, w.z, acc);
        acc = fmaf(x.w, w.w, acc);
    }
    float cur = __fadd_rn(acc, s[OFF_B3 + k]);
    out[((long long)t * BATCH + b) * 10 + k] = lif_step(mem3, cur);
}

__global__ void __launch_bounds__(256, 2) snn_kernel(
    const float* __restrict__ x,
    const float* __restrict__ W1, const float* __restrict__ b1,
    const float* __restrict__ W2, const float* __restrict__ b2,
    const float* __restrict__ W3, const float* __restrict__ b3,
    float* __restrict__ out)
{
    extern __shared__ float s[];
    const int b    = blockIdx.x;
    const int tid  = threadIdx.x;
    const int lane = tid & 31;
    const int w    = tid >> 5;

    // --- weights -> smem ---
    for (int i = tid; i < 600; i += 256) {
        int oc = i / 50, r = i % 50, ic = r / 25, k = r % 25;
        s[OFF_W1 + (oc * 25 + k) * 2 + ic] = W1[i];
    }
    // paired conv1 weights: [oc][ry-1][kx][{(ry,ic0),(ry-1,ic0),(ry,ic1),(ry-1,ic1)}]
    for (int i = tid; i < 960; i += 256) {
        int q = i & 3, idx = i >> 2;
        int kx = idx % 5, ryp = (idx / 5) % 4, oc = idx / 20;
        int ry = ryp + 1;
        int ic = q >> 1;
        int useKy = (q & 1) ? (ry - 1) : ry;
        s[OFF_W1P + i] = W1[oc * 50 + ic * 25 + useKy * 5 + kx];
    }
    for (int i = tid; i < 9600; i += 256) {
        int oc = i / 300, r = i % 300, ic = r / 25, k = r % 25;
        s[OFF_W2 + oc * 300 + k * 12 + ic] = W2[i];
    }
    for (int i = tid; i < 8000; i += 256) {
        int k = i / 800, q = i % 800;
        s[OFF_W3 + k * 804 + q] = W3[i];
    }
    for (int i = tid; i < 12; i += 256) s[OFF_B1 + i] = b1[i];
    for (int i = tid; i < 32; i += 256) s[OFF_B2 + i] = b2[i];
    for (int i = tid; i < 12; i += 256) s[OFF_B3 + i] = (i < 10) ? b3[i] : 0.f;
    __syncthreads();

    float mem1r[12];
    #pragma unroll
    for (int k = 0; k < 12; k++) mem1r[k] = 0.f;
    float mem2r[4];
    #pragma unroll
    for (int k = 0; k < 4; k++) mem2r[k] = 0.f;
    float mem3r = 0.f;

    // stage2 positions: m<3 -> p = 8m + w; m=3 -> p=24, warp 7 only
    const bool has4 = (w == 7);
    int pim[4], pjm[4];
    #pragma unroll
    for (int m = 0; m < 4; m++) {
        int p = (m < 3) ? (8 * m + w) : 24;
        pim[m] = p / 5;
        pjm[m] = p % 5;
    }

    for (int t = 0; t < T_STEPS; t++) {
        // ============ phase A: FC(t-1) on warp0 || x-load + stage1 =========
        if (w == 0) {
            if (t > 0 && lane < 10) fc_stage(s, mem3r, t - 1, b, lane, out);
        } else {
            // x[t][b] -> smem [ic][row][36]: float4 loads + float4 stores
            const float4* gx4 = reinterpret_cast<const float4*>(
                x + ((long long)t * BATCH + b) * 2048);
            for (int q = tid - 32; q < 512; q += 224) {
                float4 v = gx4[q];
                int ic = q >> 8;             // 256 f4 per channel
                int r  = (q >> 3) & 31;      // 8 f4 per row
                int c4 = q & 7;
                *reinterpret_cast<float4*>(
                    s + OFF_X + ic * XIC + r * XR + c4 * 4) = v;
            }
            asm volatile("bar.sync 1, 224;" ::: "memory");

            if (tid < 228) {
                // ocg by thread-half (warp-uniform ocb -> broadcast weight loads)
                const int task = tid - 32;
                const int ocg = (task < 98) ? 0 : 1;
                const int pos = (task < 98) ? task : (task - 98);
                const int i1 = pos / 7, jp = pos % 7;
                const int cb = 4 * jp;
                const int ocb = ocg * 6;
                const float* x0b = s + OFF_X + cb;          // ic0
                const float* x1b = s + OFF_X + XIC + cb;    // ic1

                // --- ry = 0: scalar, side0 (conv row 2i1, ky=0) ---
                float a0s[24];
                #pragma unroll
                for (int k = 0; k < 24; k++) a0s[k] = 0.f;
                {
                    float4 u0 = *reinterpret_cast<const float4*>(
                        x0b + (2 * i1) * XR);
                    float4 u1 = *reinterpret_cast<const float4*>(
                        x0b + (2 * i1) * XR + 4);
                    float4 v0 = *reinterpret_cast<const float4*>(
                        x1b + (2 * i1) * XR);
                    float4 v1 = *reinterpret_cast<const float4*>(
                        x1b + (2 * i1) * XR + 4);
                    float w0f[8] = {u0.x,u0.y,u0.z,u0.w,u1.x,u1.y,u1.z,u1.w};
                    float w1f[8] = {v0.x,v0.y,v0.z,v0.w,v1.x,v1.y,v1.z,v1.w};
                    #pragma unroll
                    for (int kx = 0; kx < 5; kx++)
                        #pragma unroll
                        for (int oc = 0; oc < 6; oc++) {
                            int base = (((ocb + oc) * 4 + 0) * 5 + kx) * 4;
                            float wx = s[OFF_W1P + base + 1];   // ky=0, ic0
                            float wy = s[OFF_W1P + base + 3];   // ky=0, ic1
                            #pragma unroll
                            for (int c = 0; c < 4; c++) {
                                float a = a0s[oc * 4 + c];
                                a = fmaf(wx, w0f[kx + c], a);
                                a = fmaf(wy, w1f[kx + c], a);
                                a0s[oc * 4 + c] = a;
                            }
                        }
                }
                u64 P[24];
                #pragma unroll
                for (int k = 0; k < 24; k++) P[k] = pack2(a0s[k], 0.f);

                // --- ry = 1..4: paired (side0 ky=ry, side1 ky=ry-1) ---
                #pragma unroll
                for (int ry = 1; ry <= 4; ry++) {
                    float4 u0 = *reinterpret_cast<const float4*>(
                        x0b + (2 * i1 + ry) * XR);
                    float4 u1 = *reinterpret_cast<const float4*>(
                        x0b + (2 * i1 + ry) * XR + 4);
                    float4 v0 = *reinterpret_cast<const float4*>(
                        x1b + (2 * i1 + ry) * XR);
                    float4 v1 = *reinterpret_cast<const float4*>(
                        x1b + (2 * i1 + ry) * XR + 4);
                    float w0f[8] = {u0.x,u0.y,u0.z,u0.w,u1.x,u1.y,u1.z,u1.w};
                    float w1f[8] = {v0.x,v0.y,v0.z,v0.w,v1.x,v1.y,v1.z,v1.w};
                    u64 xd[16];
                    #pragma unroll
                    for (int j = 0; j < 8; j++) {
                        xd[2 * j]     = pack2(w0f[j], w0f[j]);  // ic0 dup
                        xd[2 * j + 1] = pack2(w1f[j], w1f[j]);  // ic1 dup
                    }
                    #pragma unroll
                    for (int kx = 0; kx < 5; kx++)
                        #pragma unroll
                        for (int oc = 0; oc < 6; oc++) {
                            ulonglong2 wq = *reinterpret_cast<const ulonglong2*>(
                                s + OFF_W1P +
                                (((ocb + oc) * 4 + (ry - 1)) * 5 + kx) * 4);
                            #pragma unroll
                            for (int c = 0; c < 4; c++) {
                                ffma2(P[oc * 4 + c], wq.x, xd[2 * (kx + c)]);
                                ffma2(P[oc * 4 + c], wq.y, xd[2 * (kx + c) + 1]);
                            }
                        }
                }
                float a1s[24];
                #pragma unroll
                for (int k = 0; k < 24; k++) unpack2(a0s[k], a1s[k], P[k]);

                // --- ry = 5: scalar, side1 (conv row 2i1+1, ky=4) ---
                {
                    float4 u0 = *reinterpret_cast<const float4*>(
                        x0b + (2 * i1 + 5) * XR);
                    float4 u1 = *reinterpret_cast<const float4*>(
                        x0b + (2 * i1 + 5) * XR + 4);
                    float4 v0 = *reinterpret_cast<const float4*>(
                        x1b + (2 * i1 + 5) * XR);
                    float4 v1 = *reinterpret_cast<const float4*>(
                        x1b + (2 * i1 + 5) * XR + 4);
                    float w0f[8] = {u0.x,u0.y,u0.z,u0.w,u1.x,u1.y,u1.z,u1.w};
                    float w1f[8] = {v0.x,v0.y,v0.z,v0.w,v1.x,v1.y,v1.z,v1.w};
                    #pragma unroll
                    for (int kx = 0; kx < 5; kx++)
                        #pragma unroll
                        for (int oc = 0; oc < 6; oc++) {
                            int base = (((ocb + oc) * 4 + 3) * 5 + kx) * 4;
                            float wx = s[OFF_W1P + base + 0];   // ky=4, ic0
                            float wy = s[OFF_W1P + base + 2];   // ky=4, ic1
                            #pragma unroll
                            for (int c = 0; c < 4; c++) {
                                float a = a1s[oc * 4 + c];
                                a = fmaf(wx, w0f[kx + c], a);
                                a = fmaf(wy, w1f[kx + c], a);
                                a1s[oc * 4 + c] = a;
                            }
                        }
                }

                // pool + LIF + dual-layout spike stores
                #pragma unroll
                for (int oc = 0; oc < 6; oc++) {
                    float p0 = fmaxf(fmaxf(a0s[oc*4+0], a0s[oc*4+1]),
                                     fmaxf(a1s[oc*4+0], a1s[oc*4+1]));
                    float p1 = fmaxf(fmaxf(a0s[oc*4+2], a0s[oc*4+3]),
                                     fmaxf(a1s[oc*4+2], a1s[oc*4+3]));
                    float bias = s[OFF_B1 + ocb + oc];
                    float sp0 = lif_step(mem1r[oc * 2 + 0], __fadd_rn(p0, bias));
                    float sp1 = lif_step(mem1r[oc * 2 + 1], __fadd_rn(p1, bias));
                    const int r = i1, ch = ocb + oc;
                    const int rpA = r >> 1, qA = r & 1;
                    const int c0 = 2 * jp, c1 = 2 * jp + 1;
                    s[OFF_S1A + ((c0 * 7 + rpA) * 12 + ch) * 2 + qA] = sp0;
                    s[OFF_S1A + ((c1 * 7 + rpA) * 12 + ch) * 2 + qA] = sp1;
                    if (r >= 1 && r <= 12) {
                        const int rpB = (r - 1) >> 1, qB = 1 - (r & 1);
                        s[OFF_S1B + ((c0 * 6 + rpB) * 12 + ch) * 2 + qB] = sp0;
                        s[OFF_S1B + ((c1 * 6 + rpB) * 12 + ch) * 2 + qB] = sp1;
                    }
                }
            }
        }
        __syncthreads();

        // ============ phase B: stage 2, column-rolling FFMA2 ===============
        {
            const float* wocb = s + OFF_W2 + lane * 300;
            u64 A0[4], A1[4];
            #pragma unroll
            for (int m = 0; m < 4; m++) { A0[m] = 0ULL; A1[m] = 0ULL; }

            for (int ky = 0; ky < 5; ky++) {
                const float* pb[4];
                int cs4[4];
                #pragma unroll
                for (int m = 0; m < 4; m++) {
                    int ra = 2 * pim[m] + ky;
                    if (ra & 1) {
                        cs4[m] = 144;
                        pb[m] = s + OFF_S1B + ((ra - 1) >> 1) * 24
                                + 2 * pjm[m] * 144;
                    } else {
                        cs4[m] = 168;
                        pb[m] = s + OFF_S1A + (ra >> 1) * 24
                                + 2 * pjm[m] * 168;
                    }
                }
                u64 wcur[12], wprev[12];
                #pragma unroll
                for (int j = 0; j < 12; j++) { wcur[j] = 0ULL; wprev[j] = 0ULL; }
                #pragma unroll
                for (int c = 0; c < 6; c++) {
                    #pragma unroll
                    for (int j = 0; j < 12; j++) wprev[j] = wcur[j];
                    if (c < 5) {
                        const float4* wv4 = reinterpret_cast<const float4*>(
                            wocb + (ky * 5 + c) * 12);
                        float4 w0 = wv4[0], w1 = wv4[1], w2 = wv4[2];
                        wcur[0]  = pack2(w0.x, w0.x); wcur[1]  = pack2(w0.y, w0.y);
                        wcur[2]  = pack2(w0.z, w0.z); wcur[3]  = pack2(w0.w, w0.w);
                        wcur[4]  = pack2(w1.x, w1.x); wcur[5]  = pack2(w1.y, w1.y);
                        wcur[6]  = pack2(w1.z, w1.z); wcur[7]  = pack2(w1.w, w1.w);
                        wcur[8]  = pack2(w2.x, w2.x); wcur[9]  = pack2(w2.y, w2.y);
                        wcur[10] = pack2(w2.z, w2.z); wcur[11] = pack2(w2.w, w2.w);
                    }
                    #pragma unroll
                    for (int m = 0; m < 4; m++) {
                        if (m < 3 || has4) {
                            const ulonglong2* xc =
                                reinterpret_cast<const ulonglong2*>(
                                    pb[m] + c * cs4[m]);
                            ulonglong2 x0 = xc[0], x1 = xc[1], x2 = xc[2];
                            ulonglong2 x3 = xc[3], x4 = xc[4], x5 = xc[5];
                            if (c < 5) {
                                ffma2(A0[m], wcur[0],  x0.x);
                                ffma2(A0[m], wcur[1],  x0.y);
                                ffma2(A0[m], wcur[2],  x1.x);
                                ffma2(A0[m], wcur[3],  x1.y);
                                ffma2(A0[m], wcur[4],  x2.x);
                                ffma2(A0[m], wcur[5],  x2.y);
                                ffma2(A0[m], wcur[6],  x3.x);
                                ffma2(A0[m], wcur[7],  x3.y);
                                ffma2(A0[m], wcur[8],  x4.x);
                                ffma2(A0[m], wcur[9],  x4.y);
                                ffma2(A0[m], wcur[10], x5.x);
                                ffma2(A0[m], wcur[11], x5.y);
                            }
                            if (c >= 1) {
                                ffma2(A1[m], wprev[0],  x0.x);
                                ffma2(A1[m], wprev[1],  x0.y);
                                ffma2(A1[m], wprev[2],  x1.x);
                                ffma2(A1[m], wprev[3],  x1.y);
                                ffma2(A1[m], wprev[4],  x2.x);
                                ffma2(A1[m], wprev[5],  x2.y);
                                ffma2(A1[m], wprev[6],  x3.x);
                                ffma2(A1[m], wprev[7],  x3.y);
                                ffma2(A1[m], wprev[8],  x4.x);
                                ffma2(A1[m], wprev[9],  x4.y);
                                ffma2(A1[m], wprev[10], x5.x);
                                ffma2(A1[m], wprev[11], x5.y);
                            }
                        }
                    }
                }
            }
            #pragma unroll
            for (int m = 0; m < 4; m++) {
                if (m < 3 || has4) {
                    int p = (m < 3) ? (8 * m + w) : 24;
                    float a00, a10, a01, a11;
                    unpack2(a00, a10, A0[m]);
                    unpack2(a01, a11, A1[m]);
                    float pm = fmaxf(fmaxf(a00, a01), fmaxf(a10, a11));
                    float cur = __fadd_rn(pm, s[OFF_B2 + lane]);
                    s[OFF_S2 + lane * 25 + p] = lif_step(mem2r[m], cur);
                }
            }
        }
        __syncthreads();
    }

    if (w == 0 && lane < 10)
        fc_stage(s, mem3r, T_STEPS - 1, b, lane, out);
}

extern "C" void kernel_launch(void* const* d_in, const int* in_sizes, int n_in,
                              void* d_out, int out_size) {
    const float* x  = (const float*)d_in[0];
    const float* W1 = (const float*)d_in[1];
    const float* b1 = (const float*)d_in[2];
    const float* W2 = (const float*)d_in[3];
    const float* b2 = (const float*)d_in[4];
    const float* W3 = (const float*)d_in[5];
    const float* b3 = (const float*)d_in[6];
    float* out = (float*)d_out;

    cudaFuncSetAttribute(snn_kernel,
                         cudaFuncAttributeMaxDynamicSharedMemorySize,
                         SMEM_BYTES);
    snn_kernel<<<BATCH, 256, SMEM_BYTES>>>(x, W1, b1, W2, b2, W3, b3, out);
}

// round 15
// speedup vs baseline: 1.1741x; 1.1741x over previous
#include <cuda_runtime.h>

// ---------------------------------------------------------------------------
// Bit-exact fused SNN kernel, v13 = R12 (best, 2018us) + p24 SMSP-balance
// split: stage2 position 24's two column-pair accumulators are computed by
// warp 7 (A0 half) and warp 0 (A1 half, owner) instead of warp 7 alone,
// equalizing per-SMSP FFMA2 counts in phase B (7800 everywhere, was 8400 on
// SMSP3). Combine via 32-float scratch + bar.sync 2,64 (max is exact, any
// order bitwise identical). Predicate-only change: no new live registers.
// PROTECTED arithmetic (rel_err == 0.0 invariant):
//   conv: per-output sequential FMA in (ky, kx, ic) order
//   FC:   sequential FMA q = 0..799
//   LIF:  m' = fsub(fma(0.95, m, cur), reset)
//   pool-then-bias
// FFMA2 = two INDEPENDENT IEEE fma.rn; pairing never mixes chains.
// NO prefetch (R8/R9/R10/R11/R13 all regressed via register-cap spills).
// ---------------------------------------------------------------------------

#define T_STEPS 100
#define BATCH   256

typedef unsigned long long u64;

// smem layout (float offsets)
constexpr int OFF_W1  = 0;       // w1 cl [oc][ky][kx][ic2]          = 600
constexpr int OFF_B1  = 600;     // 12 (+4 pad)
constexpr int OFF_W1P = 616;     // paired w1 [oc][ry-1][kx][4]      = 960
constexpr int OFF_W2  = 1576;    // w2 cl [32][25][12]               = 9600
constexpr int OFF_B2  = 11176;   // 32
constexpr int OFF_W3  = 11208;   // [10][804]                        = 8040
constexpr int OFF_B3  = 19248;   // 12
constexpr int OFF_X   = 19260;   // x cl [32 rows][66]               = 2112
constexpr int OFF_S1A = 21372;   // spk1 A [col14][rp7][ic12][2]     = 2352
constexpr int OFF_S1B = 23724;   // spk1 B [col14][rp6][ic12][2]     = 2016
constexpr int OFF_S2  = 25740;   // 800 (oc*25 + i*5 + j)
constexpr int OFF_SC  = 26540;   // 32-float p24 scratch
constexpr int SMEM_FLOATS = 26572;
constexpr int SMEM_BYTES  = SMEM_FLOATS * 4;

__device__ __forceinline__ u64 pack2(float lo, float hi) {
    u64 r;
    asm("mov.b64 %0, {%1, %2};" : "=l"(r) : "f"(lo), "f"(hi));
    return r;
}
__device__ __forceinline__ void unpack2(float& lo, float& hi, u64 v) {
    asm("mov.b64 {%0, %1}, %2;" : "=f"(lo), "=f"(hi) : "l"(v));
}
// d.lo = fma.rn(a.lo, b.lo, d.lo); d.hi = fma.rn(a.hi, b.hi, d.hi)
__device__ __forceinline__ void ffma2(u64& d, u64 a, u64 b) {
    asm("fma.rn.f32x2 %0, %1, %2, %0;" : "+l"(d) : "l"(a), "l"(b));
}

__device__ __forceinline__ float lif_step(float& mem, float cur) {
    float reset = (mem > 1.0f) ? 1.0f : 0.0f;
    float mn = __fsub_rn(__fmaf_rn(0.95f, mem, cur), reset);
    mem = mn;
    return (mn > 1.0f) ? 1.0f : 0.0f;
}

__device__ __forceinline__ void fc_stage(const float* __restrict__ s,
                                         float& mem3, int t, int b, int k,
                                         float* __restrict__ out) {
    const float4* wr = reinterpret_cast<const float4*>(s + OFF_W3 + k * 804);
    const float4* xv = reinterpret_cast<const float4*>(s + OFF_S2);
    float acc = 0.f;
    #pragma unroll 4
    for (int q = 0; q < 200; q++) {
        float4 w = wr[q], x = xv[q];
        acc = fmaf(x.x, w.x, acc);
        acc = fmaf(x.y, w.y, acc);
        acc = fmaf(x.z, w.z, acc);
        acc = fmaf(x.w, w.w, acc);
    }
    float cur = __fadd_rn(acc, s[OFF_B3 + k]);
    out[((long long)t * BATCH + b) * 10 + k] = lif_step(mem3, cur);
}

__global__ void __launch_bounds__(256, 2) snn_kernel(
    const float* __restrict__ x,
    const float* __restrict__ W1, const float* __restrict__ b1,
    const float* __restrict__ W2, const float* __restrict__ b2,
    const float* __restrict__ W3, const float* __restrict__ b3,
    float* __restrict__ out)
{
    extern __shared__ float s[];
    const int b    = blockIdx.x;
    const int tid  = threadIdx.x;
    const int lane = tid & 31;
    const int w    = tid >> 5;

    // --- weights -> smem ---
    for (int i = tid; i < 600; i += 256) {
        int oc = i / 50, r = i % 50, ic = r / 25, k = r % 25;
        s[OFF_W1 + (oc * 25 + k) * 2 + ic] = W1[i];
    }
    // paired conv1 weights: [oc][ry-1][kx][{(ry,ic0),(ry-1,ic0),(ry,ic1),(ry-1,ic1)}]
    for (int i = tid; i < 960; i += 256) {
        int q = i & 3, idx = i >> 2;
        int kx = idx % 5, ryp = (idx / 5) % 4, oc = idx / 20;
        int ry = ryp + 1;
        int ic = q >> 1;
        int useKy = (q & 1) ? (ry - 1) : ry;
        s[OFF_W1P + i] = W1[oc * 50 + ic * 25 + useKy * 5 + kx];
    }
    for (int i = tid; i < 9600; i += 256) {
        int oc = i / 300, r = i % 300, ic = r / 25, k = r % 25;
        s[OFF_W2 + oc * 300 + k * 12 + ic] = W2[i];
    }
    for (int i = tid; i < 8000; i += 256) {
        int k = i / 800, q = i % 800;
        s[OFF_W3 + k * 804 + q] = W3[i];
    }
    for (int i = tid; i < 12; i += 256) s[OFF_B1 + i] = b1[i];
    for (int i = tid; i < 32; i += 256) s[OFF_B2 + i] = b2[i];
    for (int i = tid; i < 12; i += 256) s[OFF_B3 + i] = (i < 10) ? b3[i] : 0.f;
    __syncthreads();

    float mem1r[12];
    #pragma unroll
    for (int k = 0; k < 12; k++) mem1r[k] = 0.f;
    float mem2r[4];
    #pragma unroll
    for (int k = 0; k < 4; k++) mem2r[k] = 0.f;
    float mem3r = 0.f;

    // stage2 positions: m<3 -> p = 8m + w (all warps).
    // p24 (m=3) SPLIT: warp 7 computes A0 half, warp 0 computes A1 half and
    // owns mem2/LIF. role24: 1 = A0 half (w7), 2 = A1 half + owner (w0).
    const int role24 = (w == 7) ? 1 : ((w == 0) ? 2 : 0);
    int pim[4], pjm[4];
    #pragma unroll
    for (int m = 0; m < 4; m++) {
        int p = (m < 3) ? (8 * m + w) : 24;
        pim[m] = p / 5;
        pjm[m] = p % 5;
    }

    for (int t = 0; t < T_STEPS; t++) {
        // ============ phase A: FC(t-1) on warp0 || x-load + stage1 =========
        if (w == 0) {
            if (t > 0 && lane < 10) fc_stage(s, mem3r, t - 1, b, lane, out);
        } else {
            const float* xg = x + ((long long)t * BATCH + b) * 2048;
            for (int idx = tid - 32; idx < 2048; idx += 224) {
                int ic = idx >> 10, pos = idx & 1023;
                int r = pos >> 5, c = pos & 31;
                s[OFF_X + r * 66 + c * 2 + ic] = xg[idx];
            }
            asm volatile("bar.sync 1, 224;" ::: "memory");

            if (tid < 228) {
                // ocg by thread-half (warp-uniform ocb -> broadcast weight loads)
                const int task = tid - 32;
                const int ocg = (task < 98) ? 0 : 1;
                const int pos = (task < 98) ? task : (task - 98);
                const int i1 = pos / 7, jp = pos % 7;
                const int cb = 4 * jp;
                const int ocb = ocg * 6;

                // --- ry = 0: scalar, side0 (conv row 2i1, ky=0) ---
                float a0s[24];
                #pragma unroll
                for (int k = 0; k < 24; k++) a0s[k] = 0.f;
                {
                    const float2* xr = reinterpret_cast<const float2*>(
                        s + OFF_X + (2 * i1) * 66 + cb * 2);
                    float2 win[8];
                    #pragma unroll
                    for (int c = 0; c < 8; c++) win[c] = xr[c];
                    #pragma unroll
                    for (int kx = 0; kx < 5; kx++)
                        #pragma unroll
                        for (int oc = 0; oc < 6; oc++) {
                            float2 wv = *reinterpret_cast<const float2*>(
                                s + OFF_W1 + ((ocb + oc) * 25 + kx) * 2);
                            #pragma unroll
                            for (int c = 0; c < 4; c++) {
                                float a = a0s[oc * 4 + c];
                                a = fmaf(wv.x, win[kx + c].x, a);
                                a = fmaf(wv.y, win[kx + c].y, a);
                                a0s[oc * 4 + c] = a;
                            }
                        }
                }
                u64 P[24];
                #pragma unroll
                for (int k = 0; k < 24; k++) P[k] = pack2(a0s[k], 0.f);

                // --- ry = 1..4: paired (side0 ky=ry, side1 ky=ry-1) ---
                #pragma unroll
                for (int ry = 1; ry <= 4; ry++) {
                    const float2* xr = reinterpret_cast<const float2*>(
                        s + OFF_X + (2 * i1 + ry) * 66 + cb * 2);
                    float2 win[8];
                    #pragma unroll
                    for (int c = 0; c < 8; c++) win[c] = xr[c];
                    u64 xd[16];
                    #pragma unroll
                    for (int j = 0; j < 8; j++) {
                        xd[2 * j]     = pack2(win[j].x, win[j].x);
                        xd[2 * j + 1] = pack2(win[j].y, win[j].y);
                    }
                    #pragma unroll
                    for (int kx = 0; kx < 5; kx++)
                        #pragma unroll
                        for (int oc = 0; oc < 6; oc++) {
                            ulonglong2 wq = *reinterpret_cast<const ulonglong2*>(
                                s + OFF_W1P +
                                (((ocb + oc) * 4 + (ry - 1)) * 5 + kx) * 4);
                            #pragma unroll
                            for (int c = 0; c < 4; c++) {
                                ffma2(P[oc * 4 + c], wq.x, xd[2 * (kx + c)]);
                                ffma2(P[oc * 4 + c], wq.y, xd[2 * (kx + c) + 1]);
                            }
                        }
                }
                float a1s[24];
                #pragma unroll
                for (int k = 0; k < 24; k++) unpack2(a0s[k], a1s[k], P[k]);

                // --- ry = 5: scalar, side1 (conv row 2i1+1, ky=4) ---
                {
                    const float2* xr = reinterpret_cast<const float2*>(
                        s + OFF_X + (2 * i1 + 5) * 66 + cb * 2);
                    float2 win[8];
                    #pragma unroll
                    for (int c = 0; c < 8; c++) win[c] = xr[c];
                    #pragma unroll
                    for (int kx = 0; kx < 5; kx++)
                        #pragma unroll
                        for (int oc = 0; oc < 6; oc++) {
                            float2 wv = *reinterpret_cast<const float2*>(
                                s + OFF_W1 + ((ocb + oc) * 25 + 20 + kx) * 2);
                            #pragma unroll
                            for (int c = 0; c < 4; c++) {
                                float a = a1s[oc * 4 + c];
                                a = fmaf(wv.x, win[kx + c].x, a);
                                a = fmaf(wv.y, win[kx + c].y, a);
                                a1s[oc * 4 + c] = a;
                            }
                        }
                }

                // pool + LIF + dual-layout spike stores
                #pragma unroll
                for (int oc = 0; oc < 6; oc++) {
                    float p0 = fmaxf(fmaxf(a0s[oc*4+0], a0s[oc*4+1]),
                                     fmaxf(a1s[oc*4+0], a1s[oc*4+1]));
                    float p1 = fmaxf(fmaxf(a0s[oc*4+2], a0s[oc*4+3]),
                                     fmaxf(a1s[oc*4+2], a1s[oc*4+3]));
                    float bias = s[OFF_B1 + ocb + oc];
                    float sp0 = lif_step(mem1r[oc * 2 + 0], __fadd_rn(p0, bias));
                    float sp1 = lif_step(mem1r[oc * 2 + 1], __fadd_rn(p1, bias));
                    const int r = i1, ch = ocb + oc;
                    const int rpA = r >> 1, qA = r & 1;
                    const int c0 = 2 * jp, c1 = 2 * jp + 1;
                    s[OFF_S1A + ((c0 * 7 + rpA) * 12 + ch) * 2 + qA] = sp0;
                    s[OFF_S1A + ((c1 * 7 + rpA) * 12 + ch) * 2 + qA] = sp1;
                    if (r >= 1 && r <= 12) {
                        const int rpB = (r - 1) >> 1, qB = 1 - (r & 1);
                        s[OFF_S1B + ((c0 * 6 + rpB) * 12 + ch) * 2 + qB] = sp0;
                        s[OFF_S1B + ((c1 * 6 + rpB) * 12 + ch) * 2 + qB] = sp1;
                    }
                }
            }
        }
        __syncthreads();

        // ============ phase B: stage 2, column-rolling FFMA2 ===============
        {
            const float* wocb = s + OFF_W2 + lane * 300;
            u64 A0[4], A1[4];
            #pragma unroll
            for (int m = 0; m < 4; m++) { A0[m] = 0ULL; A1[m] = 0ULL; }

            for (int ky = 0; ky < 5; ky++) {
                const float* pb[4];
                int cs4[4];
                #pragma unroll
                for (int m = 0; m < 4; m++) {
                    int ra = 2 * pim[m] + ky;
                    if (ra & 1) {
                        cs4[m] = 144;
                        pb[m] = s + OFF_S1B + ((ra - 1) >> 1) * 24
                                + 2 * pjm[m] * 144;
                    } else {
                        cs4[m] = 168;
                        pb[m] = s + OFF_S1A + (ra >> 1) * 24
                                + 2 * pjm[m] * 168;
                    }
                }
                u64 wcur[12], wprev[12];
                #pragma unroll
                for (int j = 0; j < 12; j++) { wcur[j] = 0ULL; wprev[j] = 0ULL; }
                #pragma unroll
                for (int c = 0; c < 6; c++) {
                    #pragma unroll
                    for (int j = 0; j < 12; j++) wprev[j] = wcur[j];
                    if (c < 5) {
                        const float4* wv4 = reinterpret_cast<const float4*>(
                            wocb + (ky * 5 + c) * 12);
                        float4 w0 = wv4[0], w1 = wv4[1], w2 = wv4[2];
                        wcur[0]  = pack2(w0.x, w0.x); wcur[1]  = pack2(w0.y, w0.y);
                        wcur[2]  = pack2(w0.z, w0.z); wcur[3]  = pack2(w0.w, w0.w);
                        wcur[4]  = pack2(w1.x, w1.x); wcur[5]  = pack2(w1.y, w1.y);
                        wcur[6]  = pack2(w1.z, w1.z); wcur[7]  = pack2(w1.w, w1.w);
                        wcur[8]  = pack2(w2.x, w2.x); wcur[9]  = pack2(w2.y, w2.y);
                        wcur[10] = pack2(w2.z, w2.z); wcur[11] = pack2(w2.w, w2.w);
                    }
                    #pragma unroll
                    for (int m = 0; m < 4; m++) {
                        bool act = (m < 3) || (role24 != 0);
                        if (act) {
                            bool doA0 = (c < 5) && (m < 3 || role24 == 1);
                            bool doA1 = (c >= 1) && (m < 3 || role24 == 2);
                            const ulonglong2* xc =
                                reinterpret_cast<const ulonglong2*>(
                                    pb[m] + c * cs4[m]);
                            ulonglong2 x0 = xc[0], x1 = xc[1], x2 = xc[2];
                            ulonglong2 x3 = xc[3], x4 = xc[4], x5 = xc[5];
                            if (doA0) {
                                ffma2(A0[m], wcur[0],  x0.x);
                                ffma2(A0[m], wcur[1],  x0.y);
                                ffma2(A0[m], wcur[2],  x1.x);
                                ffma2(A0[m], wcur[3],  x1.y);
                                ffma2(A0[m], wcur[4],  x2.x);
                                ffma2(A0[m], wcur[5],  x2.y);
                                ffma2(A0[m], wcur[6],  x3.x);
                                ffma2(A0[m], wcur[7],  x3.y);
                                ffma2(A0[m], wcur[8],  x4.x);
                                ffma2(A0[m], wcur[9],  x4.y);
                                ffma2(A0[m], wcur[10], x5.x);
                                ffma2(A0[m], wcur[11], x5.y);
                            }
                            if (doA1) {
                                ffma2(A1[m], wprev[0],  x0.x);
                                ffma2(A1[m], wprev[1],  x0.y);
                                ffma2(A1[m], wprev[2],  x1.x);
                                ffma2(A1[m], wprev[3],  x1.y);
                                ffma2(A1[m], wprev[4],  x2.x);
                                ffma2(A1[m], wprev[5],  x2.y);
                                ffma2(A1[m], wprev[6],  x3.x);
                                ffma2(A1[m], wprev[7],  x3.y);
                                ffma2(A1[m], wprev[8],  x4.x);
                                ffma2(A1[m], wprev[9],  x4.y);
                                ffma2(A1[m], wprev[10], x5.x);
                                ffma2(A1[m], wprev[11], x5.y);
                            }
                        }
                    }
                }
            }
            // positions m<3: unchanged epilogue
            #pragma unroll
            for (int m = 0; m < 3; m++) {
                int p = 8 * m + w;
                float a00, a10, a01, a11;
                unpack2(a00, a10, A0[m]);
                unpack2(a01, a11, A1[m]);
                float pm = fmaxf(fmaxf(a00, a01), fmaxf(a10, a11));
                float cur = __fadd_rn(pm, s[OFF_B2 + lane]);
                s[OFF_S2 + lane * 25 + p] = lif_step(mem2r[m], cur);
            }
            // p24: w7 publishes its half-max, w0 combines + LIF (max exact,
            // combine order bitwise-irrelevant)
            if (role24 == 1) {
                float a00, a10;
                unpack2(a00, a10, A0[3]);
                s[OFF_SC + lane] = fmaxf(a00, a10);
            }
            if (role24 != 0)
                asm volatile("bar.sync 2, 64;" ::: "memory");
            if (role24 == 2) {
                float a01, a11;
                unpack2(a01, a11, A1[3]);
                float pm = fmaxf(s[OFF_SC + lane], fmaxf(a01, a11));
                float cur = __fadd_rn(pm, s[OFF_B2 + lane]);
                s[OFF_S2 + lane * 25 + 24] = lif_step(mem2r[3], cur);
            }
        }
        __syncthreads();
    }

    if (w == 0 && lane < 10)
        fc_stage(s, mem3r, T_STEPS - 1, b, lane, out);
}

extern "C" void kernel_launch(void* const* d_in, const int* in_sizes, int n_in,
                              void* d_out, int out_size) {
    const float* x  = (const float*)d_in[0];
    const float* W1 = (const float*)d_in[1];
    const float* b1 = (const float*)d_in[2];
    const float* W2 = (const float*)d_in[3];
    const float* b2 = (const float*)d_in[4];
    const float* W3 = (const float*)d_in[5];
    const float* b3 = (const float*)d_in[6];
    float* out = (float*)d_out;

    cudaFuncSetAttribute(snn_kernel,
                         cudaFuncAttributeMaxDynamicSharedMemorySize,
                         SMEM_BYTES);
    snn_kernel<<<BATCH, 256, SMEM_BYTES>>>(x, W1, b1, W2, b2, W3, b3, out);
}

// round 16
// speedup vs baseline: 1.2069x; 1.0279x over previous
#include <cuda_runtime.h>

// ---------------------------------------------------------------------------
// Bit-exact fused SNN kernel, v14 = R12 (best, 2018us) + p24 SMSP-balance
// split done RIGHT: main phase-B loop is m<3 for all warps (uniform 1800
// FFMA2); position 24 handled in a separate uniform-branch block executed
// only by warp 7 (left conv column) and warp 0 (right column + LIF owner),
// 300 FFMA2 each. R15's regression came from emitting the split inside the
// unrolled main loop as predicated no-ops on warps 1-6; the separate block
// removes that. Combine via scratch + bar.sync 2,64 (max exact).
// PROTECTED arithmetic (rel_err == 0.0 invariant):
//   conv: per-output sequential FMA in (ky, kx, ic) order
//   FC:   sequential FMA q = 0..799
//   LIF:  m' = fsub(fma(0.95, m, cur), reset)
//   pool-then-bias
// FFMA2 = two INDEPENDENT IEEE fma.rn; pairing never mixes chains.
// NO prefetch (R8/R9/R10/R11/R13 all regressed via register-cap spills).
// ---------------------------------------------------------------------------

#define T_STEPS 100
#define BATCH   256

typedef unsigned long long u64;

// smem layout (float offsets)
constexpr int OFF_W1  = 0;       // w1 cl [oc][ky][kx][ic2]          = 600
constexpr int OFF_B1  = 600;     // 12 (+4 pad)
constexpr int OFF_W1P = 616;     // paired w1 [oc][ry-1][kx][4]      = 960
constexpr int OFF_W2  = 1576;    // w2 cl [32][25][12]               = 9600
constexpr int OFF_B2  = 11176;   // 32
constexpr int OFF_W3  = 11208;   // [10][804]                        = 8040
constexpr int OFF_B3  = 19248;   // 12
constexpr int OFF_X   = 19260;   // x cl [32 rows][66]               = 2112
constexpr int OFF_S1A = 21372;   // spk1 A [col14][rp7][ic12][2]     = 2352
constexpr int OFF_S1B = 23724;   // spk1 B [col14][rp6][ic12][2]     = 2016
constexpr int OFF_S2  = 25740;   // 800 (oc*25 + i*5 + j)
constexpr int OFF_SC  = 26540;   // 32-float p24 scratch
constexpr int SMEM_FLOATS = 26572;
constexpr int SMEM_BYTES  = SMEM_FLOATS * 4;

__device__ __forceinline__ u64 pack2(float lo, float hi) {
    u64 r;
    asm("mov.b64 %0, {%1, %2};" : "=l"(r) : "f"(lo), "f"(hi));
    return r;
}
__device__ __forceinline__ void unpack2(float& lo, float& hi, u64 v) {
    asm("mov.b64 {%0, %1}, %2;" : "=f"(lo), "=f"(hi) : "l"(v));
}
// d.lo = fma.rn(a.lo, b.lo, d.lo); d.hi = fma.rn(a.hi, b.hi, d.hi)
__device__ __forceinline__ void ffma2(u64& d, u64 a, u64 b) {
    asm("fma.rn.f32x2 %0, %1, %2, %0;" : "+l"(d) : "l"(a), "l"(b));
}

__device__ __forceinline__ float lif_step(float& mem, float cur) {
    float reset = (mem > 1.0f) ? 1.0f : 0.0f;
    float mn = __fsub_rn(__fmaf_rn(0.95f, mem, cur), reset);
    mem = mn;
    return (mn > 1.0f) ? 1.0f : 0.0f;
}

__device__ __forceinline__ void fc_stage(const float* __restrict__ s,
                                         float& mem3, int t, int b, int k,
                                         float* __restrict__ out) {
    const float4* wr = reinterpret_cast<const float4*>(s + OFF_W3 + k * 804);
    const float4* xv = reinterpret_cast<const float4*>(s + OFF_S2);
    float acc = 0.f;
    #pragma unroll 4
    for (int q = 0; q < 200; q++) {
        float4 w = wr[q], x = xv[q];
        acc = fmaf(x.x, w.x, acc);
        acc = fmaf(x.y, w.y, acc);
        acc = fmaf(x.z, w.z, acc);
        acc = fmaf(x.w, w.w, acc);
    }
    float cur = __fadd_rn(acc, s[OFF_B3 + k]);
    out[((long long)t * BATCH + b) * 10 + k] = lif_step(mem3, cur);
}

__global__ void __launch_bounds__(256, 2) snn_kernel(
    const float* __restrict__ x,
    const float* __restrict__ W1, const float* __restrict__ b1,
    const float* __restrict__ W2, const float* __restrict__ b2,
    const float* __restrict__ W3, const float* __restrict__ b3,
    float* __restrict__ out)
{
    extern __shared__ float s[];
    const int b    = blockIdx.x;
    const int tid  = threadIdx.x;
    const int lane = tid & 31;
    const int w    = tid >> 5;

    // --- weights -> smem ---
    for (int i = tid; i < 600; i += 256) {
        int oc = i / 50, r = i % 50, ic = r / 25, k = r % 25;
        s[OFF_W1 + (oc * 25 + k) * 2 + ic] = W1[i];
    }
    // paired conv1 weights: [oc][ry-1][kx][{(ry,ic0),(ry-1,ic0),(ry,ic1),(ry-1,ic1)}]
    for (int i = tid; i < 960; i += 256) {
        int q = i & 3, idx = i >> 2;
        int kx = idx % 5, ryp = (idx / 5) % 4, oc = idx / 20;
        int ry = ryp + 1;
        int ic = q >> 1;
        int useKy = (q & 1) ? (ry - 1) : ry;
        s[OFF_W1P + i] = W1[oc * 50 + ic * 25 + useKy * 5 + kx];
    }
    for (int i = tid; i < 9600; i += 256) {
        int oc = i / 300, r = i % 300, ic = r / 25, k = r % 25;
        s[OFF_W2 + oc * 300 + k * 12 + ic] = W2[i];
    }
    for (int i = tid; i < 8000; i += 256) {
        int k = i / 800, q = i % 800;
        s[OFF_W3 + k * 804 + q] = W3[i];
    }
    for (int i = tid; i < 12; i += 256) s[OFF_B1 + i] = b1[i];
    for (int i = tid; i < 32; i += 256) s[OFF_B2 + i] = b2[i];
    for (int i = tid; i < 12; i += 256) s[OFF_B3 + i] = (i < 10) ? b3[i] : 0.f;
    __syncthreads();

    float mem1r[12];
    #pragma unroll
    for (int k = 0; k < 12; k++) mem1r[k] = 0.f;
    float mem2r[4];
    #pragma unroll
    for (int k = 0; k < 4; k++) mem2r[k] = 0.f;
    float mem3r = 0.f;

    // stage2 positions: m<3 -> p = 8m + w for ALL warps (uniform main loop).
    // p24 handled in a separate block: warp 7 = left conv column (role 1),
    // warp 0 = right column + LIF owner (role 2).
    const int role24 = (w == 7) ? 1 : ((w == 0) ? 2 : 0);
    int pim[3], pjm[3];
    #pragma unroll
    for (int m = 0; m < 3; m++) {
        int p = 8 * m + w;
        pim[m] = p / 5;
        pjm[m] = p % 5;
    }

    for (int t = 0; t < T_STEPS; t++) {
        // ============ phase A: FC(t-1) on warp0 || x-load + stage1 =========
        if (w == 0) {
            if (t > 0 && lane < 10) fc_stage(s, mem3r, t - 1, b, lane, out);
        } else {
            const float* xg = x + ((long long)t * BATCH + b) * 2048;
            for (int idx = tid - 32; idx < 2048; idx += 224) {
                int ic = idx >> 10, pos = idx & 1023;
                int r = pos >> 5, c = pos & 31;
                s[OFF_X + r * 66 + c * 2 + ic] = xg[idx];
            }
            asm volatile("bar.sync 1, 224;" ::: "memory");

            if (tid < 228) {
                // ocg by thread-half (warp-uniform ocb -> broadcast weight loads)
                const int task = tid - 32;
                const int ocg = (task < 98) ? 0 : 1;
                const int pos = (task < 98) ? task : (task - 98);
                const int i1 = pos / 7, jp = pos % 7;
                const int cb = 4 * jp;
                const int ocb = ocg * 6;

                // --- ry = 0: scalar, side0 (conv row 2i1, ky=0) ---
                float a0s[24];
                #pragma unroll
                for (int k = 0; k < 24; k++) a0s[k] = 0.f;
                {
                    const float2* xr = reinterpret_cast<const float2*>(
                        s + OFF_X + (2 * i1) * 66 + cb * 2);
                    float2 win[8];
                    #pragma unroll
                    for (int c = 0; c < 8; c++) win[c] = xr[c];
                    #pragma unroll
                    for (int kx = 0; kx < 5; kx++)
                        #pragma unroll
                        for (int oc = 0; oc < 6; oc++) {
                            float2 wv = *reinterpret_cast<const float2*>(
                                s + OFF_W1 + ((ocb + oc) * 25 + kx) * 2);
                            #pragma unroll
                            for (int c = 0; c < 4; c++) {
                                float a = a0s[oc * 4 + c];
                                a = fmaf(wv.x, win[kx + c].x, a);
                                a = fmaf(wv.y, win[kx + c].y, a);
                                a0s[oc * 4 + c] = a;
                            }
                        }
                }
                u64 P[24];
                #pragma unroll
                for (int k = 0; k < 24; k++) P[k] = pack2(a0s[k], 0.f);

                // --- ry = 1..4: paired (side0 ky=ry, side1 ky=ry-1) ---
                #pragma unroll
                for (int ry = 1; ry <= 4; ry++) {
                    const float2* xr = reinterpret_cast<const float2*>(
                        s + OFF_X + (2 * i1 + ry) * 66 + cb * 2);
                    float2 win[8];
                    #pragma unroll
                    for (int c = 0; c < 8; c++) win[c] = xr[c];
                    u64 xd[16];
                    #pragma unroll
                    for (int j = 0; j < 8; j++) {
                        xd[2 * j]     = pack2(win[j].x, win[j].x);
                        xd[2 * j + 1] = pack2(win[j].y, win[j].y);
                    }
                    #pragma unroll
                    for (int kx = 0; kx < 5; kx++)
                        #pragma unroll
                        for (int oc = 0; oc < 6; oc++) {
                            ulonglong2 wq = *reinterpret_cast<const ulonglong2*>(
                                s + OFF_W1P +
                                (((ocb + oc) * 4 + (ry - 1)) * 5 + kx) * 4);
                            #pragma unroll
                            for (int c = 0; c < 4; c++) {
                                ffma2(P[oc * 4 + c], wq.x, xd[2 * (kx + c)]);
                                ffma2(P[oc * 4 + c], wq.y, xd[2 * (kx + c) + 1]);
                            }
                        }
                }
                float a1s[24];
                #pragma unroll
                for (int k = 0; k < 24; k++) unpack2(a0s[k], a1s[k], P[k]);

                // --- ry = 5: scalar, side1 (conv row 2i1+1, ky=4) ---
                {
                    const float2* xr = reinterpret_cast<const float2*>(
                        s + OFF_X + (2 * i1 + 5) * 66 + cb * 2);
                    float2 win[8];
                    #pragma unroll
                    for (int c = 0; c < 8; c++) win[c] = xr[c];
                    #pragma unroll
                    for (int kx = 0; kx < 5; kx++)
                        #pragma unroll
                        for (int oc = 0; oc < 6; oc++) {
                            float2 wv = *reinterpret_cast<const float2*>(
                                s + OFF_W1 + ((ocb + oc) * 25 + 20 + kx) * 2);
                            #pragma unroll
                            for (int c = 0; c < 4; c++) {
                                float a = a1s[oc * 4 + c];
                                a = fmaf(wv.x, win[kx + c].x, a);
                                a = fmaf(wv.y, win[kx + c].y, a);
                                a1s[oc * 4 + c] = a;
                            }
                        }
                }

                // pool + LIF + dual-layout spike stores
                #pragma unroll
                for (int oc = 0; oc < 6; oc++) {
                    float p0 = fmaxf(fmaxf(a0s[oc*4+0], a0s[oc*4+1]),
                                     fmaxf(a1s[oc*4+0], a1s[oc*4+1]));
                    float p1 = fmaxf(fmaxf(a0s[oc*4+2], a0s[oc*4+3]),
                                     fmaxf(a1s[oc*4+2], a1s[oc*4+3]));
                    float bias = s[OFF_B1 + ocb + oc];
                    float sp0 = lif_step(mem1r[oc * 2 + 0], __fadd_rn(p0, bias));
                    float sp1 = lif_step(mem1r[oc * 2 + 1], __fadd_rn(p1, bias));
                    const int r = i1, ch = ocb + oc;
                    const int rpA = r >> 1, qA = r & 1;
                    const int c0 = 2 * jp, c1 = 2 * jp + 1;
                    s[OFF_S1A + ((c0 * 7 + rpA) * 12 + ch) * 2 + qA] = sp0;
                    s[OFF_S1A + ((c1 * 7 + rpA) * 12 + ch) * 2 + qA] = sp1;
                    if (r >= 1 && r <= 12) {
                        const int rpB = (r - 1) >> 1, qB = 1 - (r & 1);
                        s[OFF_S1B + ((c0 * 6 + rpB) * 12 + ch) * 2 + qB] = sp0;
                        s[OFF_S1B + ((c1 * 6 + rpB) * 12 + ch) * 2 + qB] = sp1;
                    }
                }
            }
        }
        __syncthreads();

        // ============ phase B: stage 2, column-rolling FFMA2, m<3 uniform ==
        {
            const float* wocb = s + OFF_W2 + lane * 300;
            u64 A0[3], A1[3];
            #pragma unroll
            for (int m = 0; m < 3; m++) { A0[m] = 0ULL; A1[m] = 0ULL; }

            for (int ky = 0; ky < 5; ky++) {
                const float* pb[3];
                int cs4[3];
                #pragma unroll
                for (int m = 0; m < 3; m++) {
                    int ra = 2 * pim[m] + ky;
                    if (ra & 1) {
                        cs4[m] = 144;
                        pb[m] = s + OFF_S1B + ((ra - 1) >> 1) * 24
                                + 2 * pjm[m] * 144;
                    } else {
                        cs4[m] = 168;
                        pb[m] = s + OFF_S1A + (ra >> 1) * 24
                                + 2 * pjm[m] * 168;
                    }
                }
                u64 wcur[12], wprev[12];
                #pragma unroll
                for (int j = 0; j < 12; j++) { wcur[j] = 0ULL; wprev[j] = 0ULL; }
                #pragma unroll
                for (int c = 0; c < 6; c++) {
                    #pragma unroll
                    for (int j = 0; j < 12; j++) wprev[j] = wcur[j];
                    if (c < 5) {
                        const float4* wv4 = reinterpret_cast<const float4*>(
                            wocb + (ky * 5 + c) * 12);
                        float4 w0 = wv4[0], w1 = wv4[1], w2 = wv4[2];
                        wcur[0]  = pack2(w0.x, w0.x); wcur[1]  = pack2(w0.y, w0.y);
                        wcur[2]  = pack2(w0.z, w0.z); wcur[3]  = pack2(w0.w, w0.w);
                        wcur[4]  = pack2(w1.x, w1.x); wcur[5]  = pack2(w1.y, w1.y);
                        wcur[6]  = pack2(w1.z, w1.z); wcur[7]  = pack2(w1.w, w1.w);
                        wcur[8]  = pack2(w2.x, w2.x); wcur[9]  = pack2(w2.y, w2.y);
                        wcur[10] = pack2(w2.z, w2.z); wcur[11] = pack2(w2.w, w2.w);
                    }
                    #pragma unroll
                    for (int m = 0; m < 3; m++) {
                        const ulonglong2* xc =
                            reinterpret_cast<const ulonglong2*>(
                                pb[m] + c * cs4[m]);
                        ulonglong2 x0 = xc[0], x1 = xc[1], x2 = xc[2];
                        ulonglong2 x3 = xc[3], x4 = xc[4], x5 = xc[5];
                        if (c < 5) {
                            ffma2(A0[m], wcur[0],  x0.x);
                            ffma2(A0[m], wcur[1],  x0.y);
                            ffma2(A0[m], wcur[2],  x1.x);
                            ffma2(A0[m], wcur[3],  x1.y);
                            ffma2(A0[m], wcur[4],  x2.x);
                            ffma2(A0[m], wcur[5],  x2.y);
                            ffma2(A0[m], wcur[6],  x3.x);
                            ffma2(A0[m], wcur[7],  x3.y);
                            ffma2(A0[m], wcur[8],  x4.x);
                            ffma2(A0[m], wcur[9],  x4.y);
                            ffma2(A0[m], wcur[10], x5.x);
                            ffma2(A0[m], wcur[11], x5.y);
                        }
                        if (c >= 1) {
                            ffma2(A1[m], wprev[0],  x0.x);
                            ffma2(A1[m], wprev[1],  x0.y);
                            ffma2(A1[m], wprev[2],  x1.x);
                            ffma2(A1[m], wprev[3],  x1.y);
                            ffma2(A1[m], wprev[4],  x2.x);
                            ffma2(A1[m], wprev[5],  x2.y);
                            ffma2(A1[m], wprev[6],  x3.x);
                            ffma2(A1[m], wprev[7],  x3.y);
                            ffma2(A1[m], wprev[8],  x4.x);
                            ffma2(A1[m], wprev[9],  x4.y);
                            ffma2(A1[m], wprev[10], x5.x);
                            ffma2(A1[m], wprev[11], x5.y);
                        }
                    }
                }
            }
            #pragma unroll
            for (int m = 0; m < 3; m++) {
                int p = 8 * m + w;
                float a00, a10, a01, a11;
                unpack2(a00, a10, A0[m]);
                unpack2(a01, a11, A1[m]);
                float pm = fmaxf(fmaxf(a00, a01), fmaxf(a10, a11));
                float cur = __fadd_rn(pm, s[OFF_B2 + lane]);
                s[OFF_S2 + lane * 25 + p] = lif_step(mem2r[m], cur);
            }

            // ---- p24 (i2=4, j2=4) in a separate uniform-branch block ----
            // role 1 (warp 7): left conv column (kx applied to window col kx)
            // role 2 (warp 0): right conv column (kx applied to col kx+1),
            //                  owner of mem2r[3] + LIF + store.
            if (role24) {
                u64 A = 0ULL;
                #pragma unroll
                for (int ky = 0; ky < 5; ky++) {
                    const int ra = 8 + ky;
                    const float* pbb;
                    int cs;
                    if (ra & 1) {
                        cs = 144;
                        pbb = s + OFF_S1B + ((ra - 1) >> 1) * 24 + 8 * 144;
                    } else {
                        cs = 168;
                        pbb = s + OFF_S1A + (ra >> 1) * 24 + 8 * 168;
                    }
                    #pragma unroll
                    for (int kx = 0; kx < 5; kx++) {
                        const float4* wv4 = reinterpret_cast<const float4*>(
                            wocb + (ky * 5 + kx) * 12);
                        float4 w0 = wv4[0], w1 = wv4[1], w2 = wv4[2];
                        u64 wp0  = pack2(w0.x, w0.x), wp1 = pack2(w0.y, w0.y);
                        u64 wp2  = pack2(w0.z, w0.z), wp3 = pack2(w0.w, w0.w);
                        u64 wp4  = pack2(w1.x, w1.x), wp5 = pack2(w1.y, w1.y);
                        u64 wp6  = pack2(w1.z, w1.z), wp7 = pack2(w1.w, w1.w);
                        u64 wp8  = pack2(w2.x, w2.x), wp9 = pack2(w2.y, w2.y);
                        u64 wp10 = pack2(w2.z, w2.z), wp11 = pack2(w2.w, w2.w);
                        int ccol = (role24 == 1) ? kx : (kx + 1);
                        const ulonglong2* xc =
                            reinterpret_cast<const ulonglong2*>(pbb + ccol * cs);
                        ulonglong2 x0 = xc[0], x1 = xc[1], x2 = xc[2];
                        ulonglong2 x3 = xc[3], x4 = xc[4], x5 = xc[5];
                        ffma2(A, wp0,  x0.x);
                        ffma2(A, wp1,  x0.y);
                        ffma2(A, wp2,  x1.x);
                        ffma2(A, wp3,  x1.y);
                        ffma2(A, wp4,  x2.x);
                        ffma2(A, wp5,  x2.y);
                        ffma2(A, wp6,  x3.x);
                        ffma2(A, wp7,  x3.y);
                        ffma2(A, wp8,  x4.x);
                        ffma2(A, wp9,  x4.y);
                        ffma2(A, wp10, x5.x);
                        ffma2(A, wp11, x5.y);
                    }
                }
                float va, vb;
                unpack2(va, vb, A);
                if (role24 == 1)
                    s[OFF_SC + lane] = fmaxf(va, vb);
                asm volatile("bar.sync 2, 64;" ::: "memory");
                if (role24 == 2) {
                    float pm = fmaxf(s[OFF_SC + lane], fmaxf(va, vb));
                    float cur = __fadd_rn(pm, s[OFF_B2 + lane]);
                    s[OFF_S2 + lane * 25 + 24] = lif_step(mem2r[3], cur);
                }
            }
        }
        __syncthreads();
    }

    if (w == 0 && lane < 10)
        fc_stage(s, mem3r, T_STEPS - 1, b, lane, out);
}

extern "C" void kernel_launch(void* const* d_in, const int* in_sizes, int n_in,
                              void* d_out, int out_size) {
    const float* x  = (const float*)d_in[0];
    const float* W1 = (const float*)d_in[1];
    const float* b1 = (const float*)d_in[2];
    const float* W2 = (const float*)d_in[3];
    const float* b2 = (const float*)d_in[4];
    const float* W3 = (const float*)d_in[5];
    const float* b3 = (const float*)d_in[6];
    float* out = (float*)d_out;

    cudaFuncSetAttribute(snn_kernel,
                         cudaFuncAttributeMaxDynamicSharedMemorySize,
                         SMEM_BYTES);
    snn_kernel<<<BATCH, 256, SMEM_BYTES>>>(x, W1, b1, W2, b2, W3, b3, out);
}